// round 1
// baseline (speedup 1.0000x reference)
#include <cuda_runtime.h>
#include <math.h>

#define E_DIM 1280
#define H_NUM 20
#define D_HEAD 64
#define T_TOK 8192
#define EPS_LN 1e-5f

// ---------------- scratch (no cudaMalloc allowed) ----------------
__device__ float g_h [T_TOK * E_DIM];
__device__ float g_qp[T_TOK * E_DIM];
__device__ float g_kp[T_TOK * E_DIM];
__device__ float g_vp[T_TOK * E_DIM];
__device__ float g_qa[T_TOK * E_DIM];   // [B*H, S, D]
__device__ float g_ka[T_TOK * E_DIM];
__device__ float g_va[T_TOK * E_DIM];
__device__ float g_ao[T_TOK * E_DIM];   // attention output, [T, E]

// ---------------- block reduce helpers ----------------
__device__ __forceinline__ void block_reduce2(float& s, float& s2, float* sh) {
    // warp reduce
    for (int o = 16; o; o >>= 1) {
        s  += __shfl_xor_sync(0xffffffffu, s,  o);
        s2 += __shfl_xor_sync(0xffffffffu, s2, o);
    }
    int w = threadIdx.x >> 5, l = threadIdx.x & 31;
    int nw = blockDim.x >> 5;
    if (l == 0) { sh[w] = s; sh[8 + w] = s2; }
    __syncthreads();
    float ts = 0.f, ts2 = 0.f;
    for (int i = 0; i < nw; i++) { ts += sh[i]; ts2 += sh[8 + i]; }
    s = ts; s2 = ts2;
    __syncthreads();
}

// ---------------- kernel 1: pre-LN of x ----------------
__global__ void ln_x_kernel(const float* __restrict__ x,
                            const float* __restrict__ w,
                            const float* __restrict__ b,
                            float* __restrict__ out) {
    __shared__ float sh[16];
    int t = blockIdx.x;
    const float* row = x + (size_t)t * E_DIM;
    float s = 0.f, s2 = 0.f;
    for (int e = threadIdx.x; e < E_DIM; e += blockDim.x) {
        float v = row[e]; s += v; s2 += v * v;
    }
    block_reduce2(s, s2, sh);
    float m  = s  * (1.0f / E_DIM);
    float var = s2 * (1.0f / E_DIM) - m * m;
    float rs = rsqrtf(var + EPS_LN);
    float* orow = out + (size_t)t * E_DIM;
    for (int e = threadIdx.x; e < E_DIM; e += blockDim.x)
        orow[e] = (row[e] - m) * rs * w[e] + b[e];
}

// ---------------- kernel 2: SGEMM  C[m,n] = sum_k A[m,k]*B[n,k] ----------------
#define BM 128
#define BN 128
#define BK 16
__global__ void gemm_nt(const float* __restrict__ A, const float* __restrict__ B,
                        float* __restrict__ C, int M, int N, int K) {
    __shared__ float As[BK][BM + 4];
    __shared__ float Bs[BK][BN + 4];
    int tid = threadIdx.x;           // 256
    int tx = tid & 15, ty = tid >> 4;
    const float* Ab = A + (size_t)(blockIdx.y * BM) * K;
    const float* Bb = B + (size_t)(blockIdx.x * BN) * K;
    float acc[8][8];
    #pragma unroll
    for (int i = 0; i < 8; i++)
        #pragma unroll
        for (int j = 0; j < 8; j++) acc[i][j] = 0.f;

    for (int k0 = 0; k0 < K; k0 += BK) {
        #pragma unroll
        for (int i = 0; i < 2; i++) {
            int idx = tid + i * 256;
            int r = idx >> 2, c4 = (idx & 3) * 4;
            float4 va = *(const float4*)(Ab + (size_t)r * K + k0 + c4);
            As[c4 + 0][r] = va.x; As[c4 + 1][r] = va.y;
            As[c4 + 2][r] = va.z; As[c4 + 3][r] = va.w;
            float4 vb = *(const float4*)(Bb + (size_t)r * K + k0 + c4);
            Bs[c4 + 0][r] = vb.x; Bs[c4 + 1][r] = vb.y;
            Bs[c4 + 2][r] = vb.z; Bs[c4 + 3][r] = vb.w;
        }
        __syncthreads();
        #pragma unroll
        for (int kk = 0; kk < BK; kk++) {
            float4 a0 = *(const float4*)&As[kk][ty * 8];
            float4 a1 = *(const float4*)&As[kk][ty * 8 + 4];
            float4 b0 = *(const float4*)&Bs[kk][tx * 8];
            float4 b1 = *(const float4*)&Bs[kk][tx * 8 + 4];
            float a_[8] = {a0.x,a0.y,a0.z,a0.w,a1.x,a1.y,a1.z,a1.w};
            float b_[8] = {b0.x,b0.y,b0.z,b0.w,b1.x,b1.y,b1.z,b1.w};
            #pragma unroll
            for (int i = 0; i < 8; i++)
                #pragma unroll
                for (int j = 0; j < 8; j++)
                    acc[i][j] = fmaf(a_[i], b_[j], acc[i][j]);
        }
        __syncthreads();
    }
    int rowb = blockIdx.y * BM + ty * 8;
    int colb = blockIdx.x * BN + tx * 8;
    #pragma unroll
    for (int i = 0; i < 8; i++)
        #pragma unroll
        for (int j = 0; j < 8; j++)
            C[(size_t)(rowb + i) * N + colb + j] = acc[i][j];
}

// ---------------- kernel 3: LN(q), LN(k), RoPE, layout rearrange ----------------
__global__ void lnrope_kernel(const float* __restrict__ qp, const float* __restrict__ kp,
                              const float* __restrict__ vp,
                              const float* __restrict__ lnqw, const float* __restrict__ lnkw,
                              const int* __restrict__ cu, int ncu,
                              float* __restrict__ qa, float* __restrict__ ka,
                              float* __restrict__ va, int S) {
    __shared__ float sh[32];
    __shared__ float qn[E_DIM], kn[E_DIM];
    __shared__ float cs[32], sn[32];
    int t = blockIdx.x;
    const float* qrow = qp + (size_t)t * E_DIM;
    const float* krow = kp + (size_t)t * E_DIM;
    const float* vrow = vp + (size_t)t * E_DIM;

    float sq = 0.f, sq2 = 0.f, sk = 0.f, sk2 = 0.f;
    for (int e = threadIdx.x; e < E_DIM; e += blockDim.x) {
        float q = qrow[e], k = krow[e];
        sq += q; sq2 += q * q; sk += k; sk2 += k * k;
    }
    // two reductions back-to-back
    block_reduce2(sq, sq2, sh);
    block_reduce2(sk, sk2, sh);
    float mq = sq * (1.0f / E_DIM);
    float rq = rsqrtf(sq2 * (1.0f / E_DIM) - mq * mq + EPS_LN);
    float mk = sk * (1.0f / E_DIM);
    float rk = rsqrtf(sk2 * (1.0f / E_DIM) - mk * mk + EPS_LN);

    // position within sequence (searchsorted semantics)
    int seg = 0;
    for (int i = 1; i < ncu; i++) if (cu[i] <= t) seg = i;
    float pos = (float)(t - cu[seg]);

    if (threadIdx.x < 32) {
        int j = threadIdx.x;
        float invf = expf(-logf(10000.0f) * (2.0f * j) / (float)D_HEAD);
        float f = pos * invf;
        cs[j] = cosf(f);
        sn[j] = sinf(f);
    }
    for (int e = threadIdx.x; e < E_DIM; e += blockDim.x) {
        qn[e] = (qrow[e] - mq) * rq * lnqw[e];
        kn[e] = (krow[e] - mk) * rk * lnkw[e];
    }
    __syncthreads();

    int b = t / S, s = t % S;
    for (int e = threadIdx.x; e < E_DIM; e += blockDim.x) {
        int h = e >> 6;          // /64
        int d = e & 63;
        int j = d & 31;
        float rotq = (d < 32) ? -qn[e + 32] : qn[e - 32];
        float rotk = (d < 32) ? -kn[e + 32] : kn[e - 32];
        float qv = qn[e] * cs[j] + rotq * sn[j];
        float kv = kn[e] * cs[j] + rotk * sn[j];
        size_t oidx = (((size_t)(b * H_NUM + h) * S) + s) * D_HEAD + d;
        qa[oidx] = qv;
        ka[oidx] = kv;
        va[oidx] = vrow[e];
    }
}

// ---------------- kernel 4: flash attention, 64x64 tiles, fp32 ----------------
// grid: (S/64, B*H), block: 128 threads
#define FLASH_SMEM (3 * 64 * 65 * 4)
__global__ void flash_kernel(const float* __restrict__ qa, const float* __restrict__ ka,
                             const float* __restrict__ va, float* __restrict__ ao,
                             int S) {
    extern __shared__ float sm[];
    float* Qs  = sm;                 // [64][65]
    float* KVs = sm + 64 * 65;       // [64][65]
    float* Ps  = sm + 2 * 64 * 65;   // [64][65]

    int bh = blockIdx.y;
    int qt = blockIdx.x;
    int b = bh / H_NUM, h = bh % H_NUM;
    const float* qbase = qa + ((size_t)bh * S + qt * 64) * D_HEAD;
    const float* kbase = ka + (size_t)bh * S * D_HEAD;
    const float* vbase = va + (size_t)bh * S * D_HEAD;

    int tid = threadIdx.x;
    int ty = tid >> 3, tx = tid & 7;   // 16 x 8

    // load Q tile pre-scaled by D^-0.5 = 0.125
    #pragma unroll
    for (int i = 0; i < 8; i++) {
        int idx = tid + i * 128;
        int r = idx >> 4, c4 = (idx & 15) * 4;
        float4 v = *(const float4*)(qbase + (size_t)r * 64 + c4);
        Qs[r * 65 + c4 + 0] = v.x * 0.125f;
        Qs[r * 65 + c4 + 1] = v.y * 0.125f;
        Qs[r * 65 + c4 + 2] = v.z * 0.125f;
        Qs[r * 65 + c4 + 3] = v.w * 0.125f;
    }

    float m[4], l[4], O[4][8];
    #pragma unroll
    for (int i = 0; i < 4; i++) {
        m[i] = -INFINITY; l[i] = 0.f;
        #pragma unroll
        for (int j = 0; j < 8; j++) O[i][j] = 0.f;
    }

    int nk = S / 64;
    for (int kt = 0; kt < nk; kt++) {
        __syncthreads();  // protect KVs (prev PV reads) & Qs first time
        // load K tile
        #pragma unroll
        for (int i = 0; i < 8; i++) {
            int idx = tid + i * 128;
            int r = idx >> 4, c4 = (idx & 15) * 4;
            float4 v = *(const float4*)(kbase + ((size_t)kt * 64 + r) * 64 + c4);
            KVs[r * 65 + c4 + 0] = v.x;
            KVs[r * 65 + c4 + 1] = v.y;
            KVs[r * 65 + c4 + 2] = v.z;
            KVs[r * 65 + c4 + 3] = v.w;
        }
        __syncthreads();

        // S = Q * K^T  (4 rows x 8 cols per thread)
        float s[4][8];
        #pragma unroll
        for (int i = 0; i < 4; i++)
            #pragma unroll
            for (int j = 0; j < 8; j++) s[i][j] = 0.f;
        for (int kk = 0; kk < 64; kk++) {
            float a_[4], b_[8];
            #pragma unroll
            for (int i = 0; i < 4; i++) a_[i] = Qs[(ty * 4 + i) * 65 + kk];
            #pragma unroll
            for (int j = 0; j < 8; j++) b_[j] = KVs[(tx * 8 + j) * 65 + kk];
            #pragma unroll
            for (int i = 0; i < 4; i++)
                #pragma unroll
                for (int j = 0; j < 8; j++)
                    s[i][j] = fmaf(a_[i], b_[j], s[i][j]);
        }

        // online softmax (row reductions across the 8 tx-lanes)
        #pragma unroll
        for (int i = 0; i < 4; i++) {
            float mx = s[i][0];
            #pragma unroll
            for (int j = 1; j < 8; j++) mx = fmaxf(mx, s[i][j]);
            #pragma unroll
            for (int o = 1; o < 8; o <<= 1)
                mx = fmaxf(mx, __shfl_xor_sync(0xffffffffu, mx, o));
            float mnew = fmaxf(m[i], mx);
            float alpha = expf(m[i] - mnew);
            m[i] = mnew;
            float rs = 0.f;
            #pragma unroll
            for (int j = 0; j < 8; j++) {
                float p = expf(s[i][j] - mnew);
                s[i][j] = p; rs += p;
            }
            #pragma unroll
            for (int o = 1; o < 8; o <<= 1)
                rs += __shfl_xor_sync(0xffffffffu, rs, o);
            l[i] = l[i] * alpha + rs;
            #pragma unroll
            for (int j = 0; j < 8; j++) {
                O[i][j] *= alpha;
                Ps[(ty * 4 + i) * 65 + tx * 8 + j] = s[i][j];
            }
        }
        __syncthreads();   // Ps written, K no longer needed

        // load V tile (overwrite KVs)
        #pragma unroll
        for (int i = 0; i < 8; i++) {
            int idx = tid + i * 128;
            int r = idx >> 4, c4 = (idx & 15) * 4;
            float4 v = *(const float4*)(vbase + ((size_t)kt * 64 + r) * 64 + c4);
            KVs[r * 65 + c4 + 0] = v.x;
            KVs[r * 65 + c4 + 1] = v.y;
            KVs[r * 65 + c4 + 2] = v.z;
            KVs[r * 65 + c4 + 3] = v.w;
        }
        __syncthreads();

        // O += P * V
        for (int kk = 0; kk < 64; kk++) {
            float p_[4], v_[8];
            #pragma unroll
            for (int i = 0; i < 4; i++) p_[i] = Ps[(ty * 4 + i) * 65 + kk];
            #pragma unroll
            for (int j = 0; j < 8; j++) v_[j] = KVs[kk * 65 + tx * 8 + j];
            #pragma unroll
            for (int i = 0; i < 4; i++)
                #pragma unroll
                for (int j = 0; j < 8; j++)
                    O[i][j] = fmaf(p_[i], v_[j], O[i][j]);
        }
    }

    // epilogue: divide by l, write to token-major [T, E]
    #pragma unroll
    for (int i = 0; i < 4; i++) {
        float inv = 1.0f / l[i];
        int srow = qt * 64 + ty * 4 + i;
        size_t tglob = (size_t)b * S + srow;
        float* orow = ao + tglob * E_DIM + h * D_HEAD + tx * 8;
        #pragma unroll
        for (int j = 0; j < 8; j++) orow[j] = O[i][j] * inv;
    }
}

// ---------------- host launcher ----------------
extern "C" void kernel_launch(void* const* d_in, const int* in_sizes, int n_in,
                              void* d_out, int out_size) {
    const float* x      = (const float*)d_in[0];
    const int*   cu     = (const int*)  d_in[1];
    const float* norm_w = (const float*)d_in[3];
    const float* norm_b = (const float*)d_in[4];
    const float* Wq     = (const float*)d_in[5];
    const float* Wk     = (const float*)d_in[6];
    const float* Wv     = (const float*)d_in[7];
    const float* Wout   = (const float*)d_in[8];
    const float* lnqw   = (const float*)d_in[9];
    const float* lnkw   = (const float*)d_in[10];

    int T   = in_sizes[0] / E_DIM;     // 8192
    int ncu = in_sizes[1];
    int B   = ncu - 1;
    int S   = T / B;

    float *h, *qp, *kp, *vp, *qa, *ka, *va, *ao;
    cudaGetSymbolAddress((void**)&h,  g_h);
    cudaGetSymbolAddress((void**)&qp, g_qp);
    cudaGetSymbolAddress((void**)&kp, g_kp);
    cudaGetSymbolAddress((void**)&vp, g_vp);
    cudaGetSymbolAddress((void**)&qa, g_qa);
    cudaGetSymbolAddress((void**)&ka, g_ka);
    cudaGetSymbolAddress((void**)&va, g_va);
    cudaGetSymbolAddress((void**)&ao, g_ao);

    // 1. pre-LN
    ln_x_kernel<<<T, 256>>>(x, norm_w, norm_b, h);

    // 2. projections
    dim3 ggrid(E_DIM / BN, T / BM);
    gemm_nt<<<ggrid, 256>>>(h, Wq, qp, T, E_DIM, E_DIM);
    gemm_nt<<<ggrid, 256>>>(h, Wk, kp, T, E_DIM, E_DIM);
    gemm_nt<<<ggrid, 256>>>(h, Wv, vp, T, E_DIM, E_DIM);

    // 3. LN(q), LN(k), RoPE, head-major rearrange
    lnrope_kernel<<<T, 256>>>(qp, kp, vp, lnqw, lnkw, cu, ncu, qa, ka, va, S);

    // 4. flash attention
    cudaFuncSetAttribute(flash_kernel, cudaFuncAttributeMaxDynamicSharedMemorySize, FLASH_SMEM);
    dim3 fgrid(S / 64, B * H_NUM);
    flash_kernel<<<fgrid, 128, FLASH_SMEM>>>(qa, ka, va, ao, S);

    // 5. output projection
    gemm_nt<<<ggrid, 256>>>(ao, Wout, (float*)d_out, T, E_DIM, E_DIM);
}

// round 3
// speedup vs baseline: 1.6063x; 1.6063x over previous
#include <cuda_runtime.h>
#include <math.h>
#include <stdint.h>

#define E_DIM 1280
#define H_NUM 20
#define D_HEAD 64
#define T_TOK 8192
#define EPS_LN 1e-5f

// ---------------- scratch (no cudaMalloc allowed) ----------------
__device__ float g_h [T_TOK * E_DIM];
__device__ float g_qp[T_TOK * E_DIM];
__device__ float g_kp[T_TOK * E_DIM];
__device__ float g_vp[T_TOK * E_DIM];
__device__ float g_qa[T_TOK * E_DIM];   // [B*H, S, D]
__device__ float g_ka[T_TOK * E_DIM];
__device__ float g_va[T_TOK * E_DIM];
__device__ float g_ao[T_TOK * E_DIM];   // attention output, [T, E]

// ---------------- block reduce helpers ----------------
__device__ __forceinline__ void block_reduce2(float& s, float& s2, float* sh) {
    for (int o = 16; o; o >>= 1) {
        s  += __shfl_xor_sync(0xffffffffu, s,  o);
        s2 += __shfl_xor_sync(0xffffffffu, s2, o);
    }
    int w = threadIdx.x >> 5, l = threadIdx.x & 31;
    int nw = blockDim.x >> 5;
    if (l == 0) { sh[w] = s; sh[8 + w] = s2; }
    __syncthreads();
    float ts = 0.f, ts2 = 0.f;
    for (int i = 0; i < nw; i++) { ts += sh[i]; ts2 += sh[8 + i]; }
    s = ts; s2 = ts2;
    __syncthreads();
}

// ---------------- kernel 1: pre-LN of x ----------------
__global__ void ln_x_kernel(const float* __restrict__ x,
                            const float* __restrict__ w,
                            const float* __restrict__ b,
                            float* __restrict__ out) {
    __shared__ float sh[16];
    int t = blockIdx.x;
    const float* row = x + (size_t)t * E_DIM;
    float s = 0.f, s2 = 0.f;
    for (int e = threadIdx.x; e < E_DIM; e += blockDim.x) {
        float v = row[e]; s += v; s2 += v * v;
    }
    block_reduce2(s, s2, sh);
    float m  = s  * (1.0f / E_DIM);
    float var = s2 * (1.0f / E_DIM) - m * m;
    float rs = rsqrtf(var + EPS_LN);
    float* orow = out + (size_t)t * E_DIM;
    for (int e = threadIdx.x; e < E_DIM; e += blockDim.x)
        orow[e] = (row[e] - m) * rs * w[e] + b[e];
}

// ---------------- TF32 tensor-core GEMM: C[m,n] = sum_k A[m,k]*B[n,k] ----------------
// block tile 128x128x32, 8 warps of 64x32, mma.sync.m16n8k8.tf32
#define BM 128
#define BN 128
#define BK 32
#define LDT 36                       // padded row stride (floats): 144B, 16B-aligned
#define GEMM_SMEM (2 * 2 * BM * LDT * 4)

__device__ __forceinline__ uint32_t f2tf32(float f) {
    uint32_t r;
    asm volatile("cvt.rna.tf32.f32 %0, %1;" : "=r"(r) : "f"(f));
    return r;
}

__global__ __launch_bounds__(256, 2)
void gemm_tf32(const float* __restrict__ A, const float* __restrict__ B,
               float* __restrict__ C, int M, int N, int K) {
    extern __shared__ float sm[];
    // layout: [buf][A(128*36) | B(128*36)]
    float* Asb[2] = { sm,                sm + 2 * BM * LDT };
    float* Bsb[2] = { sm + BM * LDT,     sm + 3 * BM * LDT };

    int tid = threadIdx.x;
    int warp = tid >> 5, lane = tid & 31;
    int wm = warp & 1, wn = warp >> 1;          // 2 x 4 warp grid
    int g = lane >> 2, t = lane & 3;            // fragment lane decomposition

    const float* Ab = A + (size_t)(blockIdx.y * BM) * K;
    const float* Bb = B + (size_t)(blockIdx.x * BN) * K;

    float acc[4][4][4];
    #pragma unroll
    for (int i = 0; i < 4; i++)
        #pragma unroll
        for (int j = 0; j < 4; j++)
            #pragma unroll
            for (int c = 0; c < 4; c++) acc[i][j][c] = 0.f;

    auto issue = [&](int k0, int buf) {
        float* As = Asb[buf];
        float* Bs = Bsb[buf];
        #pragma unroll
        for (int i = 0; i < 4; i++) {
            int idx = tid + i * 256;
            int r = idx >> 3, c4 = (idx & 7) * 4;
            uint32_t sa = (uint32_t)__cvta_generic_to_shared(As + r * LDT + c4);
            asm volatile("cp.async.cg.shared.global [%0], [%1], 16;\n"
                         :: "r"(sa), "l"(Ab + (size_t)r * K + k0 + c4));
            uint32_t sb = (uint32_t)__cvta_generic_to_shared(Bs + r * LDT + c4);
            asm volatile("cp.async.cg.shared.global [%0], [%1], 16;\n"
                         :: "r"(sb), "l"(Bb + (size_t)r * K + k0 + c4));
        }
        asm volatile("cp.async.commit_group;\n");
    };

    int NK = K / BK;
    issue(0, 0);

    for (int kt = 0; kt < NK; kt++) {
        __syncthreads();                       // prev compute on buf being refilled is done
        if (kt + 1 < NK) {
            issue((kt + 1) * BK, (kt + 1) & 1);
            asm volatile("cp.async.wait_group 1;\n");
        } else {
            asm volatile("cp.async.wait_group 0;\n");
        }
        __syncthreads();

        const float* As = Asb[kt & 1];
        const float* Bs = Bsb[kt & 1];

        #pragma unroll
        for (int ks = 0; ks < 4; ks++) {       // 4 k8-steps per BK=32
            int k0 = ks * 8;
            uint32_t af[4][4], bf[4][2];
            #pragma unroll
            for (int i = 0; i < 4; i++) {
                int r0 = wm * 64 + i * 16 + g;
                af[i][0] = f2tf32(As[r0 * LDT + k0 + t]);
                af[i][1] = f2tf32(As[(r0 + 8) * LDT + k0 + t]);
                af[i][2] = f2tf32(As[r0 * LDT + k0 + t + 4]);
                af[i][3] = f2tf32(As[(r0 + 8) * LDT + k0 + t + 4]);
            }
            #pragma unroll
            for (int j = 0; j < 4; j++) {
                int nb = wn * 32 + j * 8 + g;
                bf[j][0] = f2tf32(Bs[nb * LDT + k0 + t]);
                bf[j][1] = f2tf32(Bs[nb * LDT + k0 + t + 4]);
            }
            #pragma unroll
            for (int i = 0; i < 4; i++)
                #pragma unroll
                for (int j = 0; j < 4; j++) {
                    asm volatile(
                        "mma.sync.aligned.m16n8k8.row.col.f32.tf32.tf32.f32 "
                        "{%0,%1,%2,%3}, {%4,%5,%6,%7}, {%8,%9}, {%0,%1,%2,%3};\n"
                        : "+f"(acc[i][j][0]), "+f"(acc[i][j][1]),
                          "+f"(acc[i][j][2]), "+f"(acc[i][j][3])
                        : "r"(af[i][0]), "r"(af[i][1]), "r"(af[i][2]), "r"(af[i][3]),
                          "r"(bf[j][0]), "r"(bf[j][1]));
                }
        }
    }

    // epilogue
    int rb = blockIdx.y * BM + wm * 64;
    int cb = blockIdx.x * BN + wn * 32;
    #pragma unroll
    for (int i = 0; i < 4; i++) {
        #pragma unroll
        for (int j = 0; j < 4; j++) {
            int r0 = rb + i * 16 + g;
            int c0 = cb + j * 8 + t * 2;
            *(float2*)&C[(size_t)r0 * N + c0]       = make_float2(acc[i][j][0], acc[i][j][1]);
            *(float2*)&C[(size_t)(r0 + 8) * N + c0] = make_float2(acc[i][j][2], acc[i][j][3]);
        }
    }
}

// ---------------- kernel 3: LN(q), LN(k), RoPE, layout rearrange ----------------
__global__ void lnrope_kernel(const float* __restrict__ qp, const float* __restrict__ kp,
                              const float* __restrict__ vp,
                              const float* __restrict__ lnqw, const float* __restrict__ lnkw,
                              const int* __restrict__ cu, int ncu,
                              float* __restrict__ qa, float* __restrict__ ka,
                              float* __restrict__ va, int S) {
    __shared__ float sh[32];
    __shared__ float qn[E_DIM], kn[E_DIM];
    __shared__ float cs[32], sn[32];
    int t = blockIdx.x;
    const float* qrow = qp + (size_t)t * E_DIM;
    const float* krow = kp + (size_t)t * E_DIM;
    const float* vrow = vp + (size_t)t * E_DIM;

    float sq = 0.f, sq2 = 0.f, sk = 0.f, sk2 = 0.f;
    for (int e = threadIdx.x; e < E_DIM; e += blockDim.x) {
        float q = qrow[e], k = krow[e];
        sq += q; sq2 += q * q; sk += k; sk2 += k * k;
    }
    block_reduce2(sq, sq2, sh);
    block_reduce2(sk, sk2, sh);
    float mq = sq * (1.0f / E_DIM);
    float rq = rsqrtf(sq2 * (1.0f / E_DIM) - mq * mq + EPS_LN);
    float mk = sk * (1.0f / E_DIM);
    float rk = rsqrtf(sk2 * (1.0f / E_DIM) - mk * mk + EPS_LN);

    int seg = 0;
    for (int i = 1; i < ncu; i++) if (cu[i] <= t) seg = i;
    float pos = (float)(t - cu[seg]);

    if (threadIdx.x < 32) {
        int j = threadIdx.x;
        float invf = expf(-logf(10000.0f) * (2.0f * j) / (float)D_HEAD);
        float f = pos * invf;
        cs[j] = cosf(f);
        sn[j] = sinf(f);
    }
    for (int e = threadIdx.x; e < E_DIM; e += blockDim.x) {
        qn[e] = (qrow[e] - mq) * rq * lnqw[e];
        kn[e] = (krow[e] - mk) * rk * lnkw[e];
    }
    __syncthreads();

    int b = t / S, s = t % S;
    for (int e = threadIdx.x; e < E_DIM; e += blockDim.x) {
        int h = e >> 6;
        int d = e & 63;
        int j = d & 31;
        float rotq = (d < 32) ? -qn[e + 32] : qn[e - 32];
        float rotk = (d < 32) ? -kn[e + 32] : kn[e - 32];
        float qv = qn[e] * cs[j] + rotq * sn[j];
        float kv = kn[e] * cs[j] + rotk * sn[j];
        size_t oidx = (((size_t)(b * H_NUM + h) * S) + s) * D_HEAD + d;
        qa[oidx] = qv;
        ka[oidx] = kv;
        va[oidx] = vrow[e];
    }
}

// ---------------- kernel 4: flash attention, 64x64 tiles, fp32 ----------------
#define FLASH_SMEM (3 * 64 * 65 * 4)
__global__ void flash_kernel(const float* __restrict__ qa, const float* __restrict__ ka,
                             const float* __restrict__ va, float* __restrict__ ao,
                             int S) {
    extern __shared__ float smf[];
    float* Qs  = smf;
    float* KVs = smf + 64 * 65;
    float* Ps  = smf + 2 * 64 * 65;

    int bh = blockIdx.y;
    int qt = blockIdx.x;
    int b = bh / H_NUM, h = bh % H_NUM;
    const float* qbase = qa + ((size_t)bh * S + qt * 64) * D_HEAD;
    const float* kbase = ka + (size_t)bh * S * D_HEAD;
    const float* vbase = va + (size_t)bh * S * D_HEAD;

    int tid = threadIdx.x;
    int ty = tid >> 3, tx = tid & 7;

    #pragma unroll
    for (int i = 0; i < 8; i++) {
        int idx = tid + i * 128;
        int r = idx >> 4, c4 = (idx & 15) * 4;
        float4 v = *(const float4*)(qbase + (size_t)r * 64 + c4);
        Qs[r * 65 + c4 + 0] = v.x * 0.125f;
        Qs[r * 65 + c4 + 1] = v.y * 0.125f;
        Qs[r * 65 + c4 + 2] = v.z * 0.125f;
        Qs[r * 65 + c4 + 3] = v.w * 0.125f;
    }

    float m[4], l[4], O[4][8];
    #pragma unroll
    for (int i = 0; i < 4; i++) {
        m[i] = -INFINITY; l[i] = 0.f;
        #pragma unroll
        for (int j = 0; j < 8; j++) O[i][j] = 0.f;
    }

    int nk = S / 64;
    for (int kt = 0; kt < nk; kt++) {
        __syncthreads();
        #pragma unroll
        for (int i = 0; i < 8; i++) {
            int idx = tid + i * 128;
            int r = idx >> 4, c4 = (idx & 15) * 4;
            float4 v = *(const float4*)(kbase + ((size_t)kt * 64 + r) * 64 + c4);
            KVs[r * 65 + c4 + 0] = v.x;
            KVs[r * 65 + c4 + 1] = v.y;
            KVs[r * 65 + c4 + 2] = v.z;
            KVs[r * 65 + c4 + 3] = v.w;
        }
        __syncthreads();

        float s[4][8];
        #pragma unroll
        for (int i = 0; i < 4; i++)
            #pragma unroll
            for (int j = 0; j < 8; j++) s[i][j] = 0.f;
        for (int kk = 0; kk < 64; kk++) {
            float a_[4], b_[8];
            #pragma unroll
            for (int i = 0; i < 4; i++) a_[i] = Qs[(ty * 4 + i) * 65 + kk];
            #pragma unroll
            for (int j = 0; j < 8; j++) b_[j] = KVs[(tx * 8 + j) * 65 + kk];
            #pragma unroll
            for (int i = 0; i < 4; i++)
                #pragma unroll
                for (int j = 0; j < 8; j++)
                    s[i][j] = fmaf(a_[i], b_[j], s[i][j]);
        }

        #pragma unroll
        for (int i = 0; i < 4; i++) {
            float mx = s[i][0];
            #pragma unroll
            for (int j = 1; j < 8; j++) mx = fmaxf(mx, s[i][j]);
            #pragma unroll
            for (int o = 1; o < 8; o <<= 1)
                mx = fmaxf(mx, __shfl_xor_sync(0xffffffffu, mx, o));
            float mnew = fmaxf(m[i], mx);
            float alpha = expf(m[i] - mnew);
            m[i] = mnew;
            float rs = 0.f;
            #pragma unroll
            for (int j = 0; j < 8; j++) {
                float p = expf(s[i][j] - mnew);
                s[i][j] = p; rs += p;
            }
            #pragma unroll
            for (int o = 1; o < 8; o <<= 1)
                rs += __shfl_xor_sync(0xffffffffu, rs, o);
            l[i] = l[i] * alpha + rs;
            #pragma unroll
            for (int j = 0; j < 8; j++) {
                O[i][j] *= alpha;
                Ps[(ty * 4 + i) * 65 + tx * 8 + j] = s[i][j];
            }
        }
        __syncthreads();

        #pragma unroll
        for (int i = 0; i < 8; i++) {
            int idx = tid + i * 128;
            int r = idx >> 4, c4 = (idx & 15) * 4;
            float4 v = *(const float4*)(vbase + ((size_t)kt * 64 + r) * 64 + c4);
            KVs[r * 65 + c4 + 0] = v.x;
            KVs[r * 65 + c4 + 1] = v.y;
            KVs[r * 65 + c4 + 2] = v.z;
            KVs[r * 65 + c4 + 3] = v.w;
        }
        __syncthreads();

        for (int kk = 0; kk < 64; kk++) {
            float p_[4], v_[8];
            #pragma unroll
            for (int i = 0; i < 4; i++) p_[i] = Ps[(ty * 4 + i) * 65 + kk];
            #pragma unroll
            for (int j = 0; j < 8; j++) v_[j] = KVs[kk * 65 + tx * 8 + j];
            #pragma unroll
            for (int i = 0; i < 4; i++)
                #pragma unroll
                for (int j = 0; j < 8; j++)
                    O[i][j] = fmaf(p_[i], v_[j], O[i][j]);
        }
    }

    #pragma unroll
    for (int i = 0; i < 4; i++) {
        float inv = 1.0f / l[i];
        int srow = qt * 64 + ty * 4 + i;
        size_t tglob = (size_t)b * S + srow;
        float* orow = ao + tglob * E_DIM + h * D_HEAD + tx * 8;
        #pragma unroll
        for (int j = 0; j < 8; j++) orow[j] = O[i][j] * inv;
    }
}

// ---------------- host launcher ----------------
extern "C" void kernel_launch(void* const* d_in, const int* in_sizes, int n_in,
                              void* d_out, int out_size) {
    const float* x      = (const float*)d_in[0];
    const int*   cu     = (const int*)  d_in[1];
    const float* norm_w = (const float*)d_in[3];
    const float* norm_b = (const float*)d_in[4];
    const float* Wq     = (const float*)d_in[5];
    const float* Wk     = (const float*)d_in[6];
    const float* Wv     = (const float*)d_in[7];
    const float* Wout   = (const float*)d_in[8];
    const float* lnqw   = (const float*)d_in[9];
    const float* lnkw   = (const float*)d_in[10];

    int T   = in_sizes[0] / E_DIM;
    int ncu = in_sizes[1];
    int B   = ncu - 1;
    int S   = T / B;

    float *h, *qp, *kp, *vp, *qa, *ka, *va, *ao;
    cudaGetSymbolAddress((void**)&h,  g_h);
    cudaGetSymbolAddress((void**)&qp, g_qp);
    cudaGetSymbolAddress((void**)&kp, g_kp);
    cudaGetSymbolAddress((void**)&vp, g_vp);
    cudaGetSymbolAddress((void**)&qa, g_qa);
    cudaGetSymbolAddress((void**)&ka, g_ka);
    cudaGetSymbolAddress((void**)&va, g_va);
    cudaGetSymbolAddress((void**)&ao, g_ao);

    // no static guards — set attributes unconditionally every call
    cudaFuncSetAttribute(gemm_tf32, cudaFuncAttributeMaxDynamicSharedMemorySize, GEMM_SMEM);
    cudaFuncSetAttribute(flash_kernel, cudaFuncAttributeMaxDynamicSharedMemorySize, FLASH_SMEM);

    // 1. pre-LN
    ln_x_kernel<<<T, 256>>>(x, norm_w, norm_b, h);

    // 2. projections (TF32 tensor cores)
    dim3 ggrid(E_DIM / BN, T / BM);
    gemm_tf32<<<ggrid, 256, GEMM_SMEM>>>(h, Wq, qp, T, E_DIM, E_DIM);
    gemm_tf32<<<ggrid, 256, GEMM_SMEM>>>(h, Wk, kp, T, E_DIM, E_DIM);
    gemm_tf32<<<ggrid, 256, GEMM_SMEM>>>(h, Wv, vp, T, E_DIM, E_DIM);

    // 3. LN(q), LN(k), RoPE, head-major rearrange
    lnrope_kernel<<<T, 256>>>(qp, kp, vp, lnqw, lnkw, cu, ncu, qa, ka, va, S);

    // 4. flash attention
    dim3 fgrid(S / 64, B * H_NUM);
    flash_kernel<<<fgrid, 128, FLASH_SMEM>>>(qa, ka, va, ao, S);

    // 5. output projection
    gemm_tf32<<<ggrid, 256, GEMM_SMEM>>>(ao, Wout, (float*)d_out, T, E_DIM, E_DIM);
}